// round 1
// baseline (speedup 1.0000x reference)
#include <cuda_runtime.h>

#define HIDDEN 1024
#define BB 8
#define SS 1024
#define NH 16
#define HD 64
#define SCALE 0.125f
#define FS 68   // flash smem row stride (floats)

// Scratch (no cudaMalloc allowed)
__device__ float g_Qh[BB * NH * SS * HD];
__device__ float g_Kh[BB * NH * SS * HD];
__device__ float g_Vh[BB * NH * SS * HD];
__device__ float g_Ctx[BB * SS * HIDDEN];

// ---------------------------------------------------------------------------
// C[m,n] = sum_k A[m,k] * W[n,k] + bias[n]
// mode 0: write to [b, h, s, d] layout (for QKV heads),  m=b*S+s, n=h*64+d
// mode 1: write row-major [m, n] (final output)
// ---------------------------------------------------------------------------
__global__ __launch_bounds__(256)
void gemm_bias_kernel(const float* __restrict__ A, const float* __restrict__ W,
                      const float* __restrict__ bias, float* __restrict__ C, int mode)
{
    __shared__ float As[8][128];
    __shared__ float Bs[8][128];
    const int m0 = blockIdx.y * 128;
    const int n0 = blockIdx.x * 128;
    const int tid = threadIdx.x;
    const int tx = tid & 15, ty = tid >> 4;
    const int lr = tid >> 1;            // 0..127
    const int lk = (tid & 1) << 2;      // 0 or 4

    const float* Ap = A + (size_t)(m0 + lr) * HIDDEN + lk;
    const float* Wp = W + (size_t)(n0 + lr) * HIDDEN + lk;

    float acc[8][8];
#pragma unroll
    for (int i = 0; i < 8; i++)
#pragma unroll
        for (int j = 0; j < 8; j++) acc[i][j] = 0.f;

    for (int kt = 0; kt < HIDDEN; kt += 8) {
        float4 av = *(const float4*)(Ap + kt);
        float4 wv = *(const float4*)(Wp + kt);
        __syncthreads();
        As[lk + 0][lr] = av.x; As[lk + 1][lr] = av.y;
        As[lk + 2][lr] = av.z; As[lk + 3][lr] = av.w;
        Bs[lk + 0][lr] = wv.x; Bs[lk + 1][lr] = wv.y;
        Bs[lk + 2][lr] = wv.z; Bs[lk + 3][lr] = wv.w;
        __syncthreads();
#pragma unroll
        for (int k = 0; k < 8; k++) {
            float4 a0 = *(const float4*)&As[k][ty * 4];
            float4 a1 = *(const float4*)&As[k][64 + ty * 4];
            float4 b0 = *(const float4*)&Bs[k][tx * 4];
            float4 b1 = *(const float4*)&Bs[k][64 + tx * 4];
            float ar[8] = {a0.x, a0.y, a0.z, a0.w, a1.x, a1.y, a1.z, a1.w};
            float br[8] = {b0.x, b0.y, b0.z, b0.w, b1.x, b1.y, b1.z, b1.w};
#pragma unroll
            for (int i = 0; i < 8; i++)
#pragma unroll
                for (int j = 0; j < 8; j++)
                    acc[i][j] = fmaf(ar[i], br[j], acc[i][j]);
        }
    }

#pragma unroll
    for (int i = 0; i < 8; i++) {
        int row = m0 + ((i < 4) ? (ty * 4 + i) : (64 + ty * 4 + (i - 4)));
#pragma unroll
        for (int j = 0; j < 8; j++) {
            int col = n0 + ((j < 4) ? (tx * 4 + j) : (64 + tx * 4 + (j - 4)));
            float cv = acc[i][j] + bias[col];
            if (mode == 0) {
                int b = row >> 10, s = row & 1023;
                int h = col >> 6,  d = col & 63;
                C[(((size_t)(b * NH + h)) * SS + s) * HD + d] = cv;
            } else {
                C[(size_t)row * HIDDEN + col] = cv;
            }
        }
    }
}

// ---------------------------------------------------------------------------
// Flash attention: one CTA per (b, h, 64-row q tile). 256 threads = 16x16.
// Q/K/P stored d-major (transposed) in smem so inner loops are float4 loads.
// ---------------------------------------------------------------------------
__global__ __launch_bounds__(256)
void flash_kernel(const float* __restrict__ Qh, const float* __restrict__ Kh,
                  const float* __restrict__ Vh, const float* __restrict__ attn_bias,
                  const float* __restrict__ zoom, float* __restrict__ Ctx)
{
    extern __shared__ float smem[];
    float* QsT = smem;               // [64(d)][FS] -> Q[r][d] at QsT[d*FS + r]
    float* KsT = smem + 64 * FS;     // K[c][d] at KsT[d*FS + c]
    float* Vs  = smem + 2 * 64 * FS; // V[t][d] at Vs[t*FS + d]
    float* PsT = smem + 3 * 64 * FS; // P[r][t] at PsT[t*FS + r]

    const int tid = threadIdx.x;
    const int tx = tid & 15, ty = tid >> 4;
    const int qt = blockIdx.x, h = blockIdx.y, b = blockIdx.z;
    const int s0 = qt * 64;

    const float* gQ = Qh + (((size_t)(b * NH + h)) * SS + s0) * HD;
    const float* gK = Kh + ((size_t)(b * NH + h)) * SS * HD;
    const float* gV = Vh + ((size_t)(b * NH + h)) * SS * HD;
    const float* gB = attn_bias + (size_t)b * SS * SS;

    // Load Q tile transposed, pre-scaled
#pragma unroll
    for (int li = 0; li < 4; li++) {
        int lin = tid + li * 256;
        int r = lin >> 4, c4 = (lin & 15) << 2;
        float4 v = ((const float4*)gQ)[lin];
        QsT[(c4 + 0) * FS + r] = v.x * SCALE;
        QsT[(c4 + 1) * FS + r] = v.y * SCALE;
        QsT[(c4 + 2) * FS + r] = v.z * SCALE;
        QsT[(c4 + 3) * FS + r] = v.w * SCALE;
    }

    float acc[4][4];
#pragma unroll
    for (int i = 0; i < 4; i++)
#pragma unroll
        for (int j = 0; j < 4; j++) acc[i][j] = 0.f;
    float mi[4]  = {-3.0e38f, -3.0e38f, -3.0e38f, -3.0e38f};
    float li_[4] = {0.f, 0.f, 0.f, 0.f};

    for (int kt = 0; kt < 16; kt++) {
        const int t0 = kt * 64;
        __syncthreads();   // previous P.V done before overwriting K/V
#pragma unroll
        for (int li = 0; li < 4; li++) {
            int lin = tid + li * 256;
            int r = lin >> 4, c4 = (lin & 15) << 2;
            float4 kv = ((const float4*)(gK + (size_t)t0 * HD))[lin];
            KsT[(c4 + 0) * FS + r] = kv.x;
            KsT[(c4 + 1) * FS + r] = kv.y;
            KsT[(c4 + 2) * FS + r] = kv.z;
            KsT[(c4 + 3) * FS + r] = kv.w;
            float4 vv = ((const float4*)(gV + (size_t)t0 * HD))[lin];
            *(float4*)&Vs[r * FS + c4] = vv;
        }
        __syncthreads();

        // S = (Q*scale) . K^T   (64x64x64)
        float sc[4][4];
#pragma unroll
        for (int i = 0; i < 4; i++)
#pragma unroll
            for (int j = 0; j < 4; j++) sc[i][j] = 0.f;
#pragma unroll 16
        for (int kk = 0; kk < 64; kk++) {
            float4 qv = *(const float4*)&QsT[kk * FS + ty * 4];
            float4 kv = *(const float4*)&KsT[kk * FS + tx * 4];
            float qa[4] = {qv.x, qv.y, qv.z, qv.w};
            float ka[4] = {kv.x, kv.y, kv.z, kv.w};
#pragma unroll
            for (int i = 0; i < 4; i++)
#pragma unroll
                for (int j = 0; j < 4; j++)
                    sc[i][j] = fmaf(qa[i], ka[j], sc[i][j]);
        }

        // biases + online softmax (row groups of 16 threads = half warp)
#pragma unroll
        for (int i = 0; i < 4; i++) {
            int rg = s0 + ty * 4 + i;
            const float* brow = gB + (size_t)rg * SS + t0;
            const float* zrow = zoom + (rg - t0 + 1023);  // ze = zoom[rg - cg + 1023]
            float mx = -3.0e38f;
#pragma unroll
            for (int j = 0; j < 4; j++) {
                int cl = tx * 4 + j;
                float sv = sc[i][j] + zrow[-cl] + brow[cl];
                sc[i][j] = sv;
                mx = fmaxf(mx, sv);
            }
#pragma unroll
            for (int off = 8; off; off >>= 1)
                mx = fmaxf(mx, __shfl_xor_sync(0xffffffffu, mx, off, 16));
            float mnew  = fmaxf(mi[i], mx);
            float alpha = __expf(mi[i] - mnew);
            mi[i] = mnew;
            float rs = 0.f;
#pragma unroll
            for (int j = 0; j < 4; j++) {
                float p = __expf(sc[i][j] - mnew);
                sc[i][j] = p;
                rs += p;
            }
#pragma unroll
            for (int off = 8; off; off >>= 1)
                rs += __shfl_xor_sync(0xffffffffu, rs, off, 16);
            li_[i] = li_[i] * alpha + rs;
#pragma unroll
            for (int j = 0; j < 4; j++) acc[i][j] *= alpha;
#pragma unroll
            for (int j = 0; j < 4; j++)
                PsT[(tx * 4 + j) * FS + ty * 4 + i] = sc[i][j];
        }
        __syncthreads();

        // O += P.V   (64x64x64)
#pragma unroll 16
        for (int kk = 0; kk < 64; kk++) {
            float4 pv = *(const float4*)&PsT[kk * FS + ty * 4];
            float4 vv = *(const float4*)&Vs[kk * FS + tx * 4];
            float pa[4] = {pv.x, pv.y, pv.z, pv.w};
            float va[4] = {vv.x, vv.y, vv.z, vv.w};
#pragma unroll
            for (int i = 0; i < 4; i++)
#pragma unroll
                for (int j = 0; j < 4; j++)
                    acc[i][j] = fmaf(pa[i], va[j], acc[i][j]);
        }
    }

    // normalize + store ctx in [b, s, h*d] (GEMM-ready)
#pragma unroll
    for (int i = 0; i < 4; i++) {
        float inv = 1.f / li_[i];
        int rg = s0 + ty * 4 + i;
        float4 o = make_float4(acc[i][0] * inv, acc[i][1] * inv,
                               acc[i][2] * inv, acc[i][3] * inv);
        *(float4*)(Ctx + ((size_t)(b * SS + rg)) * HIDDEN + h * HD + tx * 4) = o;
    }
}

extern "C" void kernel_launch(void* const* d_in, const int* in_sizes, int n_in,
                              void* d_out, int out_size)
{
    const float* q    = (const float*)d_in[0];
    const float* k    = (const float*)d_in[1];
    const float* v    = (const float*)d_in[2];
    const float* ab   = (const float*)d_in[3];
    const float* Wq   = (const float*)d_in[4];
    const float* bq   = (const float*)d_in[5];
    const float* Wk   = (const float*)d_in[6];
    const float* bk   = (const float*)d_in[7];
    const float* Wv   = (const float*)d_in[8];
    const float* bv   = (const float*)d_in[9];
    const float* Wo   = (const float*)d_in[10];
    const float* bo   = (const float*)d_in[11];
    const float* zoom = (const float*)d_in[12];

    float *Qh, *Kh, *Vh, *Ctx;
    cudaGetSymbolAddress((void**)&Qh,  g_Qh);
    cudaGetSymbolAddress((void**)&Kh,  g_Kh);
    cudaGetSymbolAddress((void**)&Vh,  g_Vh);
    cudaGetSymbolAddress((void**)&Ctx, g_Ctx);

    const int smem_flash = 4 * 64 * FS * (int)sizeof(float);
    cudaFuncSetAttribute(flash_kernel, cudaFuncAttributeMaxDynamicSharedMemorySize,
                         smem_flash);

    dim3 gg(HIDDEN / 128, (BB * SS) / 128);
    gemm_bias_kernel<<<gg, 256>>>(q, Wq, bq, Qh, 0);
    gemm_bias_kernel<<<gg, 256>>>(k, Wk, bk, Kh, 0);
    gemm_bias_kernel<<<gg, 256>>>(v, Wv, bv, Vh, 0);

    dim3 gf(SS / 64, NH, BB);
    flash_kernel<<<gf, 256, smem_flash>>>(Qh, Kh, Vh, ab, zoom, Ctx);

    gemm_bias_kernel<<<gg, 256>>>(Ctx, Wo, bo, (float*)d_out, 1);
}

// round 4
// speedup vs baseline: 1.2666x; 1.2666x over previous
#include <cuda_runtime.h>
#include <cuda_bf16.h>
#include <cstdint>
#include <cstring>

#define HIDDEN 1024
#define BB 8
#define SS 1024
#define NH 16
#define HD 64
#define SCALE 0.125f
#define FS 68   // flash smem row stride (floats)

// Scratch (no cudaMalloc allowed)
__device__ float g_Qh[BB * NH * SS * HD];
__device__ float g_Kh[BB * NH * SS * HD];
__device__ float g_Vh[BB * NH * SS * HD];
__device__ float g_Ctx[BB * SS * HIDDEN];

__device__ __forceinline__ uint32_t b2u(__nv_bfloat162 h) {
    uint32_t u; memcpy(&u, &h, 4); return u;
}

__device__ __forceinline__ void mma16816(float* c, const uint32_t* a, const uint32_t* b) {
    asm volatile(
        "mma.sync.aligned.m16n8k16.row.col.f32.bf16.bf16.f32 "
        "{%0,%1,%2,%3}, {%4,%5,%6,%7}, {%8,%9}, {%0,%1,%2,%3};"
        : "+f"(c[0]), "+f"(c[1]), "+f"(c[2]), "+f"(c[3])
        : "r"(a[0]), "r"(a[1]), "r"(a[2]), "r"(a[3]), "r"(b[0]), "r"(b[1]));
}

// ---------------------------------------------------------------------------
// Tensor-core GEMM, split-precision bf16 (3 mma passes -> fp32-grade error):
// C[m,n] = sum_k A[m,k] * W[n,k] + bias[n]
// 128x128 tile/CTA, 8 warps (2x4), 64x32 per warp, K-chunk 64 in smem.
// Smem row stride 72 bf16 (144B) -> conflict-free fragment loads.
// mode 0: write [b, h, s, d] head layout; mode 1: row-major [m, n]
// ---------------------------------------------------------------------------
#define RSTRIDE 72            // bf16 elements per smem row (144 bytes)
#define TILE_B (128 * RSTRIDE * 2)   // 18432 bytes per tile
#define GEMM_SMEM (4 * TILE_B)       // Ah, Al, Bh, Bl

__global__ __launch_bounds__(256)
void gemm_tc_kernel(const float* __restrict__ A, const float* __restrict__ W,
                    const float* __restrict__ bias, float* __restrict__ C, int mode)
{
    extern __shared__ char dsm[];
    char* sAh = dsm;
    char* sAl = dsm + TILE_B;
    char* sBh = dsm + 2 * TILE_B;
    char* sBl = dsm + 3 * TILE_B;

    const int tid = threadIdx.x;
    const int wid = tid >> 5, lane = tid & 31;
    const int lr = lane >> 2, lc = lane & 3;
    const int n0 = blockIdx.x * 128, m0 = blockIdx.y * 128;
    const int wm = (wid >> 2) * 64;   // warp m offset (0 or 64)
    const int wn = (wid & 3) * 32;    // warp n offset

    float acc[4][4][4];
#pragma unroll
    for (int i = 0; i < 4; i++)
#pragma unroll
        for (int j = 0; j < 4; j++)
#pragma unroll
            for (int r = 0; r < 4; r++) acc[i][j][r] = 0.f;

    for (int kt = 0; kt < 16; kt++) {
        __syncthreads();
        // load + split-convert A and W chunks (128 rows x 64 fp32 each)
#pragma unroll
        for (int li = 0; li < 8; li++) {
            int idx = tid + li * 256;
            int row = idx >> 4, c4 = idx & 15;
            uint32_t soff = row * (RSTRIDE * 2) + c4 * 8;

            float4 va = *(const float4*)(A + (size_t)(m0 + row) * HIDDEN + kt * 64 + c4 * 4);
            __nv_bfloat162 ah01 = __floats2bfloat162_rn(va.x, va.y);
            __nv_bfloat162 ah23 = __floats2bfloat162_rn(va.z, va.w);
            float2 af01 = __bfloat1622float2(ah01);
            float2 af23 = __bfloat1622float2(ah23);
            __nv_bfloat162 al01 = __floats2bfloat162_rn(va.x - af01.x, va.y - af01.y);
            __nv_bfloat162 al23 = __floats2bfloat162_rn(va.z - af23.x, va.w - af23.y);
            *(uint2*)(sAh + soff) = make_uint2(b2u(ah01), b2u(ah23));
            *(uint2*)(sAl + soff) = make_uint2(b2u(al01), b2u(al23));

            float4 vb = *(const float4*)(W + (size_t)(n0 + row) * HIDDEN + kt * 64 + c4 * 4);
            __nv_bfloat162 bh01 = __floats2bfloat162_rn(vb.x, vb.y);
            __nv_bfloat162 bh23 = __floats2bfloat162_rn(vb.z, vb.w);
            float2 bf01 = __bfloat1622float2(bh01);
            float2 bf23 = __bfloat1622float2(bh23);
            __nv_bfloat162 bl01 = __floats2bfloat162_rn(vb.x - bf01.x, vb.y - bf01.y);
            __nv_bfloat162 bl23 = __floats2bfloat162_rn(vb.z - bf23.x, vb.w - bf23.y);
            *(uint2*)(sBh + soff) = make_uint2(b2u(bh01), b2u(bh23));
            *(uint2*)(sBl + soff) = make_uint2(b2u(bl01), b2u(bl23));
        }
        __syncthreads();

#pragma unroll
        for (int j = 0; j < 4; j++) {          // 4 k16 steps in the chunk
            const uint32_t kb = j * 32;        // byte offset of k16 step
            uint32_t Bhf[4][2], Blf[4][2];
#pragma unroll
            for (int jn = 0; jn < 4; jn++) {
                uint32_t boff = (wn + jn * 8 + lr) * (RSTRIDE * 2) + kb + lc * 4;
                Bhf[jn][0] = *(const uint32_t*)(sBh + boff);
                Bhf[jn][1] = *(const uint32_t*)(sBh + boff + 16);
                Blf[jn][0] = *(const uint32_t*)(sBl + boff);
                Blf[jn][1] = *(const uint32_t*)(sBl + boff + 16);
            }
#pragma unroll
            for (int i = 0; i < 4; i++) {
                uint32_t aoff = (wm + i * 16 + lr) * (RSTRIDE * 2) + kb + lc * 4;
                uint32_t Ahf[4], Alf[4];
                Ahf[0] = *(const uint32_t*)(sAh + aoff);
                Ahf[1] = *(const uint32_t*)(sAh + aoff + 8 * (RSTRIDE * 2));
                Ahf[2] = *(const uint32_t*)(sAh + aoff + 16);
                Ahf[3] = *(const uint32_t*)(sAh + aoff + 8 * (RSTRIDE * 2) + 16);
                Alf[0] = *(const uint32_t*)(sAl + aoff);
                Alf[1] = *(const uint32_t*)(sAl + aoff + 8 * (RSTRIDE * 2));
                Alf[2] = *(const uint32_t*)(sAl + aoff + 16);
                Alf[3] = *(const uint32_t*)(sAl + aoff + 8 * (RSTRIDE * 2) + 16);
#pragma unroll
                for (int jn = 0; jn < 4; jn++) {
                    mma16816(acc[i][jn], Ahf, Bhf[jn]);
                    mma16816(acc[i][jn], Ahf, Blf[jn]);
                    mma16816(acc[i][jn], Alf, Bhf[jn]);
                }
            }
        }
    }

    // epilogue: c0,c1 -> (row, col..col+1); c2,c3 -> (row+8, col..col+1)
#pragma unroll
    for (int i = 0; i < 4; i++) {
#pragma unroll
        for (int jn = 0; jn < 4; jn++) {
            int row = m0 + wm + i * 16 + lr;
            int col = n0 + wn + jn * 8 + lc * 2;
            float2 v0 = make_float2(acc[i][jn][0] + bias[col],
                                    acc[i][jn][1] + bias[col + 1]);
            float2 v1 = make_float2(acc[i][jn][2] + bias[col],
                                    acc[i][jn][3] + bias[col + 1]);
            if (mode == 0) {
                int b0_ = row >> 10, s0_ = row & 1023;
                int h = col >> 6, d = col & 63;
                *(float2*)(C + (((size_t)(b0_ * NH + h)) * SS + s0_) * HD + d) = v0;
                int row8 = row + 8;
                int b1_ = row8 >> 10, s1_ = row8 & 1023;
                *(float2*)(C + (((size_t)(b1_ * NH + h)) * SS + s1_) * HD + d) = v1;
            } else {
                *(float2*)(C + (size_t)row * HIDDEN + col) = v0;
                *(float2*)(C + (size_t)(row + 8) * HIDDEN + col) = v1;
            }
        }
    }
}

// ---------------------------------------------------------------------------
// Flash attention: one CTA per (b, h, 64-row q tile). 256 threads = 16x16.
// ---------------------------------------------------------------------------
__global__ __launch_bounds__(256)
void flash_kernel(const float* __restrict__ Qh, const float* __restrict__ Kh,
                  const float* __restrict__ Vh, const float* __restrict__ attn_bias,
                  const float* __restrict__ zoom, float* __restrict__ Ctx)
{
    extern __shared__ float smem[];
    float* QsT = smem;               // [64(d)][FS] -> Q[r][d] at QsT[d*FS + r]
    float* KsT = smem + 64 * FS;     // K[c][d] at KsT[d*FS + c]
    float* Vs  = smem + 2 * 64 * FS; // V[t][d] at Vs[t*FS + d]
    float* PsT = smem + 3 * 64 * FS; // P[r][t] at PsT[t*FS + r]

    const int tid = threadIdx.x;
    const int tx = tid & 15, ty = tid >> 4;
    const int qt = blockIdx.x, h = blockIdx.y, b = blockIdx.z;
    const int s0 = qt * 64;

    const float* gQ = Qh + (((size_t)(b * NH + h)) * SS + s0) * HD;
    const float* gK = Kh + ((size_t)(b * NH + h)) * SS * HD;
    const float* gV = Vh + ((size_t)(b * NH + h)) * SS * HD;
    const float* gB = attn_bias + (size_t)b * SS * SS;

#pragma unroll
    for (int li = 0; li < 4; li++) {
        int lin = tid + li * 256;
        int r = lin >> 4, c4 = (lin & 15) << 2;
        float4 v = ((const float4*)gQ)[lin];
        QsT[(c4 + 0) * FS + r] = v.x * SCALE;
        QsT[(c4 + 1) * FS + r] = v.y * SCALE;
        QsT[(c4 + 2) * FS + r] = v.z * SCALE;
        QsT[(c4 + 3) * FS + r] = v.w * SCALE;
    }

    float acc[4][4];
#pragma unroll
    for (int i = 0; i < 4; i++)
#pragma unroll
        for (int j = 0; j < 4; j++) acc[i][j] = 0.f;
    float mi[4]  = {-3.0e38f, -3.0e38f, -3.0e38f, -3.0e38f};
    float li_[4] = {0.f, 0.f, 0.f, 0.f};

    for (int kt = 0; kt < 16; kt++) {
        const int t0 = kt * 64;
        __syncthreads();
#pragma unroll
        for (int li = 0; li < 4; li++) {
            int lin = tid + li * 256;
            int r = lin >> 4, c4 = (lin & 15) << 2;
            float4 kv = ((const float4*)(gK + (size_t)t0 * HD))[lin];
            KsT[(c4 + 0) * FS + r] = kv.x;
            KsT[(c4 + 1) * FS + r] = kv.y;
            KsT[(c4 + 2) * FS + r] = kv.z;
            KsT[(c4 + 3) * FS + r] = kv.w;
            float4 vv = ((const float4*)(gV + (size_t)t0 * HD))[lin];
            *(float4*)&Vs[r * FS + c4] = vv;
        }
        __syncthreads();

        float sc[4][4];
#pragma unroll
        for (int i = 0; i < 4; i++)
#pragma unroll
            for (int j = 0; j < 4; j++) sc[i][j] = 0.f;
#pragma unroll 16
        for (int kk = 0; kk < 64; kk++) {
            float4 qv = *(const float4*)&QsT[kk * FS + ty * 4];
            float4 kv = *(const float4*)&KsT[kk * FS + tx * 4];
            float qa[4] = {qv.x, qv.y, qv.z, qv.w};
            float ka[4] = {kv.x, kv.y, kv.z, kv.w};
#pragma unroll
            for (int i = 0; i < 4; i++)
#pragma unroll
                for (int j = 0; j < 4; j++)
                    sc[i][j] = fmaf(qa[i], ka[j], sc[i][j]);
        }

#pragma unroll
        for (int i = 0; i < 4; i++) {
            int rg = s0 + ty * 4 + i;
            const float* brow = gB + (size_t)rg * SS + t0;
            const float* zrow = zoom + (rg - t0 + 1023);
            float mx = -3.0e38f;
#pragma unroll
            for (int j = 0; j < 4; j++) {
                int cl = tx * 4 + j;
                float sv = sc[i][j] + zrow[-cl] + brow[cl];
                sc[i][j] = sv;
                mx = fmaxf(mx, sv);
            }
#pragma unroll
            for (int off = 8; off; off >>= 1)
                mx = fmaxf(mx, __shfl_xor_sync(0xffffffffu, mx, off, 16));
            float mnew  = fmaxf(mi[i], mx);
            float alpha = __expf(mi[i] - mnew);
            mi[i] = mnew;
            float rs = 0.f;
#pragma unroll
            for (int j = 0; j < 4; j++) {
                float p = __expf(sc[i][j] - mnew);
                sc[i][j] = p;
                rs += p;
            }
#pragma unroll
            for (int off = 8; off; off >>= 1)
                rs += __shfl_xor_sync(0xffffffffu, rs, off, 16);
            li_[i] = li_[i] * alpha + rs;
#pragma unroll
            for (int j = 0; j < 4; j++) acc[i][j] *= alpha;
#pragma unroll
            for (int j = 0; j < 4; j++)
                PsT[(tx * 4 + j) * FS + ty * 4 + i] = sc[i][j];
        }
        __syncthreads();

#pragma unroll 16
        for (int kk = 0; kk < 64; kk++) {
            float4 pv = *(const float4*)&PsT[kk * FS + ty * 4];
            float4 vv = *(const float4*)&Vs[kk * FS + tx * 4];
            float pa[4] = {pv.x, pv.y, pv.z, pv.w};
            float va[4] = {vv.x, vv.y, vv.z, vv.w};
#pragma unroll
            for (int i = 0; i < 4; i++)
#pragma unroll
                for (int j = 0; j < 4; j++)
                    acc[i][j] = fmaf(pa[i], va[j], acc[i][j]);
        }
    }

#pragma unroll
    for (int i = 0; i < 4; i++) {
        float inv = 1.f / li_[i];
        int rg = s0 + ty * 4 + i;
        float4 o = make_float4(acc[i][0] * inv, acc[i][1] * inv,
                               acc[i][2] * inv, acc[i][3] * inv);
        *(float4*)(Ctx + ((size_t)(b * SS + rg)) * HIDDEN + h * HD + tx * 4) = o;
    }
}

extern "C" void kernel_launch(void* const* d_in, const int* in_sizes, int n_in,
                              void* d_out, int out_size)
{
    const float* q    = (const float*)d_in[0];
    const float* k    = (const float*)d_in[1];
    const float* v    = (const float*)d_in[2];
    const float* ab   = (const float*)d_in[3];
    const float* Wq   = (const float*)d_in[4];
    const float* bq   = (const float*)d_in[5];
    const float* Wk   = (const float*)d_in[6];
    const float* bk   = (const float*)d_in[7];
    const float* Wv   = (const float*)d_in[8];
    const float* bv   = (const float*)d_in[9];
    const float* Wo   = (const float*)d_in[10];
    const float* bo   = (const float*)d_in[11];
    const float* zoom = (const float*)d_in[12];

    float *Qh, *Kh, *Vh, *Ctx;
    cudaGetSymbolAddress((void**)&Qh,  g_Qh);
    cudaGetSymbolAddress((void**)&Kh,  g_Kh);
    cudaGetSymbolAddress((void**)&Vh,  g_Vh);
    cudaGetSymbolAddress((void**)&Ctx, g_Ctx);

    const int smem_flash = 4 * 64 * FS * (int)sizeof(float);
    cudaFuncSetAttribute(gemm_tc_kernel,
                         cudaFuncAttributeMaxDynamicSharedMemorySize, GEMM_SMEM);
    cudaFuncSetAttribute(flash_kernel,
                         cudaFuncAttributeMaxDynamicSharedMemorySize, smem_flash);

    dim3 gg(HIDDEN / 128, (BB * SS) / 128);
    gemm_tc_kernel<<<gg, 256, GEMM_SMEM>>>(q, Wq, bq, Qh, 0);
    gemm_tc_kernel<<<gg, 256, GEMM_SMEM>>>(k, Wk, bk, Kh, 0);
    gemm_tc_kernel<<<gg, 256, GEMM_SMEM>>>(v, Wv, bv, Vh, 0);

    dim3 gf(SS / 64, NH, BB);
    flash_kernel<<<gf, 256, smem_flash>>>(Qh, Kh, Vh, ab, zoom, Ctx);

    gemm_tc_kernel<<<gg, 256, GEMM_SMEM>>>(Ctx, Wo, bo, (float*)d_out, 1);
}

// round 5
// speedup vs baseline: 1.9546x; 1.5431x over previous
#include <cuda_runtime.h>
#include <cuda_bf16.h>
#include <cstdint>
#include <cstring>

#define HIDDEN 1024
#define BB 8
#define SS 1024
#define NH 16
#define HD 64
#define SCALE 0.125f

// Scratch (no cudaMalloc allowed)
__device__ float g_Qh[BB * NH * SS * HD];
__device__ float g_Kh[BB * NH * SS * HD];
__device__ float g_Vt[BB * NH * HD * SS];   // [b,h,d,s] transposed V
__device__ float g_Ctx[BB * SS * HIDDEN];

__device__ __forceinline__ uint32_t b2u(__nv_bfloat162 h) {
    uint32_t u; memcpy(&u, &h, 4); return u;
}

__device__ __forceinline__ void mma16816(float* c, const uint32_t* a, const uint32_t* b) {
    asm volatile(
        "mma.sync.aligned.m16n8k16.row.col.f32.bf16.bf16.f32 "
        "{%0,%1,%2,%3}, {%4,%5,%6,%7}, {%8,%9}, {%0,%1,%2,%3};"
        : "+f"(c[0]), "+f"(c[1]), "+f"(c[2]), "+f"(c[3])
        : "r"(a[0]), "r"(a[1]), "r"(a[2]), "r"(a[3]), "r"(b[0]), "r"(b[1]));
}

// split fp32x4 into hi/lo bf16x2 pairs
__device__ __forceinline__ void split4(float4 v, uint2& hi, uint2& lo) {
    __nv_bfloat162 h01 = __floats2bfloat162_rn(v.x, v.y);
    __nv_bfloat162 h23 = __floats2bfloat162_rn(v.z, v.w);
    float2 f01 = __bfloat1622float2(h01);
    float2 f23 = __bfloat1622float2(h23);
    __nv_bfloat162 l01 = __floats2bfloat162_rn(v.x - f01.x, v.y - f01.y);
    __nv_bfloat162 l23 = __floats2bfloat162_rn(v.z - f23.x, v.w - f23.y);
    hi = make_uint2(b2u(h01), b2u(h23));
    lo = make_uint2(b2u(l01), b2u(l23));
}

// ---------------------------------------------------------------------------
// Tensor-core GEMM, split-precision bf16 (3 mma passes -> fp32-grade error):
// C[m,n] = sum_k A[m,k] * W[n,k] + bias[n]
// mode 0: [b,h,s,d] layout; mode 1: row-major; mode 2: V-transposed [b,h,d,s]
// ---------------------------------------------------------------------------
#define RSTRIDE 72            // bf16 elements per smem row (144 bytes)
#define TILE_B (128 * RSTRIDE * 2)
#define GEMM_SMEM (4 * TILE_B)

__global__ __launch_bounds__(256)
void gemm_tc_kernel(const float* __restrict__ A, const float* __restrict__ W,
                    const float* __restrict__ bias, float* __restrict__ C, int mode)
{
    extern __shared__ char dsm[];
    char* sAh = dsm;
    char* sAl = dsm + TILE_B;
    char* sBh = dsm + 2 * TILE_B;
    char* sBl = dsm + 3 * TILE_B;

    const int tid = threadIdx.x;
    const int wid = tid >> 5, lane = tid & 31;
    const int lr = lane >> 2, lc = lane & 3;
    const int n0 = blockIdx.x * 128, m0 = blockIdx.y * 128;
    const int wm = (wid >> 2) * 64;
    const int wn = (wid & 3) * 32;

    float acc[4][4][4];
#pragma unroll
    for (int i = 0; i < 4; i++)
#pragma unroll
        for (int j = 0; j < 4; j++)
#pragma unroll
            for (int r = 0; r < 4; r++) acc[i][j][r] = 0.f;

    for (int kt = 0; kt < 16; kt++) {
        __syncthreads();
#pragma unroll
        for (int li = 0; li < 8; li++) {
            int idx = tid + li * 256;
            int row = idx >> 4, c4 = idx & 15;
            uint32_t soff = row * (RSTRIDE * 2) + c4 * 8;
            uint2 hi, lo;
            split4(*(const float4*)(A + (size_t)(m0 + row) * HIDDEN + kt * 64 + c4 * 4), hi, lo);
            *(uint2*)(sAh + soff) = hi; *(uint2*)(sAl + soff) = lo;
            split4(*(const float4*)(W + (size_t)(n0 + row) * HIDDEN + kt * 64 + c4 * 4), hi, lo);
            *(uint2*)(sBh + soff) = hi; *(uint2*)(sBl + soff) = lo;
        }
        __syncthreads();

#pragma unroll
        for (int j = 0; j < 4; j++) {
            const uint32_t kb = j * 32;
            uint32_t Bhf[4][2], Blf[4][2];
#pragma unroll
            for (int jn = 0; jn < 4; jn++) {
                uint32_t boff = (wn + jn * 8 + lr) * (RSTRIDE * 2) + kb + lc * 4;
                Bhf[jn][0] = *(const uint32_t*)(sBh + boff);
                Bhf[jn][1] = *(const uint32_t*)(sBh + boff + 16);
                Blf[jn][0] = *(const uint32_t*)(sBl + boff);
                Blf[jn][1] = *(const uint32_t*)(sBl + boff + 16);
            }
#pragma unroll
            for (int i = 0; i < 4; i++) {
                uint32_t aoff = (wm + i * 16 + lr) * (RSTRIDE * 2) + kb + lc * 4;
                uint32_t Ahf[4], Alf[4];
                Ahf[0] = *(const uint32_t*)(sAh + aoff);
                Ahf[1] = *(const uint32_t*)(sAh + aoff + 8 * (RSTRIDE * 2));
                Ahf[2] = *(const uint32_t*)(sAh + aoff + 16);
                Ahf[3] = *(const uint32_t*)(sAh + aoff + 8 * (RSTRIDE * 2) + 16);
                Alf[0] = *(const uint32_t*)(sAl + aoff);
                Alf[1] = *(const uint32_t*)(sAl + aoff + 8 * (RSTRIDE * 2));
                Alf[2] = *(const uint32_t*)(sAl + aoff + 16);
                Alf[3] = *(const uint32_t*)(sAl + aoff + 8 * (RSTRIDE * 2) + 16);
#pragma unroll
                for (int jn = 0; jn < 4; jn++) {
                    mma16816(acc[i][jn], Ahf, Bhf[jn]);
                    mma16816(acc[i][jn], Ahf, Blf[jn]);
                    mma16816(acc[i][jn], Alf, Bhf[jn]);
                }
            }
        }
    }

#pragma unroll
    for (int i = 0; i < 4; i++) {
#pragma unroll
        for (int jn = 0; jn < 4; jn++) {
            int row = m0 + wm + i * 16 + lr;
            int col = n0 + wn + jn * 8 + lc * 2;
            float2 v0 = make_float2(acc[i][jn][0] + bias[col],
                                    acc[i][jn][1] + bias[col + 1]);
            float2 v1 = make_float2(acc[i][jn][2] + bias[col],
                                    acc[i][jn][3] + bias[col + 1]);
            int row8 = row + 8;
            if (mode == 0) {
                int b0_ = row >> 10, s0_ = row & 1023;
                int h = col >> 6, d = col & 63;
                *(float2*)(C + (((size_t)(b0_ * NH + h)) * SS + s0_) * HD + d) = v0;
                int b1_ = row8 >> 10, s1_ = row8 & 1023;
                *(float2*)(C + (((size_t)(b1_ * NH + h)) * SS + s1_) * HD + d) = v1;
            } else if (mode == 1) {
                *(float2*)(C + (size_t)row * HIDDEN + col) = v0;
                *(float2*)(C + (size_t)row8 * HIDDEN + col) = v1;
            } else {
                // V transposed: Vt[((b*NH+h)*HD + d)*SS + s]
                int b0_ = row >> 10, s0_ = row & 1023;
                int s1_ = row8 & 1023;
                int h = col >> 6, d = col & 63;
                size_t base = (size_t)(b0_ * NH + h) * HD;
                C[(base + d) * SS + s0_]     = v0.x;
                C[(base + d + 1) * SS + s0_] = v0.y;
                C[(base + d) * SS + s1_]     = v1.x;
                C[(base + d + 1) * SS + s1_] = v1.y;
            }
        }
    }
}

// ---------------------------------------------------------------------------
// Tensor-core flash attention.
// 1 CTA per (b, h, 128 q rows), 8 warps x 16 rows, key chunks of 128.
// Q/K split bf16 hi/lo in smem (stride 144B); V pre-transposed [d][s] in gmem,
// staged as Vt[d][key] (stride 272B). P kept in registers (C-frag == A-frag).
// ---------------------------------------------------------------------------
#define QK_STR 144      // bytes per smem row for Q/K (72 bf16)
#define VT_STR 272      // bytes per smem row for Vt (136 bf16)
#define SM_QH 0
#define SM_QL (SM_QH + 128 * QK_STR)
#define SM_KH (SM_QL + 128 * QK_STR)
#define SM_KL (SM_KH + 128 * QK_STR)
#define SM_VH (SM_KL + 128 * QK_STR)
#define SM_VL (SM_VH + 64 * VT_STR)
#define SM_ZS (SM_VL + 64 * VT_STR)
#define FLASH_SMEM (SM_ZS + 1152 * 4)

__global__ __launch_bounds__(256)
void flash_tc_kernel(const float* __restrict__ Qg, const float* __restrict__ Kg,
                     const float* __restrict__ Vtg, const float* __restrict__ attn_bias,
                     const float* __restrict__ zoom, float* __restrict__ Ctx)
{
    extern __shared__ char sm[];
    float* zs = (float*)(sm + SM_ZS);

    const int tid = threadIdx.x;
    const int wid = tid >> 5, lane = tid & 31;
    const int lr = lane >> 2, lc = lane & 3;
    const int wq = wid * 16;
    const int qt = blockIdx.x, h = blockIdx.y, b = blockIdx.z;
    const int qr0 = qt * 128;

    const float* gQ  = Qg  + (((size_t)(b * NH + h)) * SS + qr0) * HD;
    const float* gK  = Kg  + ((size_t)(b * NH + h)) * SS * HD;
    const float* gVt = Vtg + ((size_t)(b * NH + h)) * HD * SS;
    const float* gB  = attn_bias + (size_t)b * SS * SS;

    // stage zoom segment: zs[u] = zoom[qr0 + u], u = row_local - key + 1023
    for (int u = tid; u < 1152; u += 256)
        zs[u] = (qr0 + u < 2047) ? zoom[qr0 + u] : 0.f;

    // load Q (128x64), scale + split
#pragma unroll
    for (int li = 0; li < 8; li++) {
        int idx = tid + li * 256;
        int row = idx >> 4, c4 = idx & 15;
        float4 v = *(const float4*)(gQ + (size_t)row * HD + c4 * 4);
        v.x *= SCALE; v.y *= SCALE; v.z *= SCALE; v.w *= SCALE;
        uint2 hi, lo;
        split4(v, hi, lo);
        uint32_t soff = row * QK_STR + c4 * 8;
        *(uint2*)(sm + SM_QH + soff) = hi;
        *(uint2*)(sm + SM_QL + soff) = lo;
    }

    float accO[8][4];
#pragma unroll
    for (int nt = 0; nt < 8; nt++)
#pragma unroll
        for (int r = 0; r < 4; r++) accO[nt][r] = 0.f;
    float mi0 = -3.0e38f, mi1 = -3.0e38f, li0 = 0.f, li1 = 0.f;

    for (int kt = 0; kt < 8; kt++) {
        const int t0 = kt * 128;
        __syncthreads();
        // K chunk 128x64
#pragma unroll
        for (int li = 0; li < 8; li++) {
            int idx = tid + li * 256;
            int row = idx >> 4, c4 = idx & 15;
            uint2 hi, lo;
            split4(*(const float4*)(gK + (size_t)(t0 + row) * HD + c4 * 4), hi, lo);
            uint32_t soff = row * QK_STR + c4 * 8;
            *(uint2*)(sm + SM_KH + soff) = hi;
            *(uint2*)(sm + SM_KL + soff) = lo;
        }
        // Vt chunk 64 x 128 keys
#pragma unroll
        for (int li = 0; li < 8; li++) {
            int idx = tid + li * 256;
            int d = idx >> 5, kg = idx & 31;
            uint2 hi, lo;
            split4(*(const float4*)(gVt + (size_t)d * SS + t0 + kg * 4), hi, lo);
            uint32_t soff = d * VT_STR + kg * 8;
            *(uint2*)(sm + SM_VH + soff) = hi;
            *(uint2*)(sm + SM_VL + soff) = lo;
        }
        __syncthreads();

        // S = Q.K^T : warp computes 16 x 128
        float sc[16][4];
#pragma unroll
        for (int nt = 0; nt < 16; nt++)
#pragma unroll
            for (int r = 0; r < 4; r++) sc[nt][r] = 0.f;

#pragma unroll
        for (int ks = 0; ks < 4; ks++) {
            const uint32_t kb = ks * 32;
            uint32_t aoff = (wq + lr) * QK_STR + kb + lc * 4;
            uint32_t Ahf[4], Alf[4];
            Ahf[0] = *(const uint32_t*)(sm + SM_QH + aoff);
            Ahf[1] = *(const uint32_t*)(sm + SM_QH + aoff + 8 * QK_STR);
            Ahf[2] = *(const uint32_t*)(sm + SM_QH + aoff + 16);
            Ahf[3] = *(const uint32_t*)(sm + SM_QH + aoff + 8 * QK_STR + 16);
            Alf[0] = *(const uint32_t*)(sm + SM_QL + aoff);
            Alf[1] = *(const uint32_t*)(sm + SM_QL + aoff + 8 * QK_STR);
            Alf[2] = *(const uint32_t*)(sm + SM_QL + aoff + 16);
            Alf[3] = *(const uint32_t*)(sm + SM_QL + aoff + 8 * QK_STR + 16);
#pragma unroll
            for (int nt = 0; nt < 16; nt++) {
                uint32_t boff = (nt * 8 + lr) * QK_STR + kb + lc * 4;
                uint32_t Bh[2], Bl[2];
                Bh[0] = *(const uint32_t*)(sm + SM_KH + boff);
                Bh[1] = *(const uint32_t*)(sm + SM_KH + boff + 16);
                Bl[0] = *(const uint32_t*)(sm + SM_KL + boff);
                Bl[1] = *(const uint32_t*)(sm + SM_KL + boff + 16);
                mma16816(sc[nt], Ahf, Bh);
                mma16816(sc[nt], Ahf, Bl);
                mma16816(sc[nt], Alf, Bh);
            }
        }

        // add attn_bias + zoom, track row maxes
        const int row_l0 = wq + lr;
        float mx0 = -3.0e38f, mx1 = -3.0e38f;
#pragma unroll
        for (int nt = 0; nt < 16; nt++) {
            int keyg = t0 + nt * 8 + lc * 2;
            const float* bp = gB + (size_t)(qr0 + row_l0) * SS + keyg;
            float2 bv0 = *(const float2*)bp;
            float2 bv1 = *(const float2*)(bp + 8 * SS);
            int u0 = row_l0 - keyg + 1023;
            sc[nt][0] += bv0.x + zs[u0];
            sc[nt][1] += bv0.y + zs[u0 - 1];
            sc[nt][2] += bv1.x + zs[u0 + 8];
            sc[nt][3] += bv1.y + zs[u0 + 7];
            mx0 = fmaxf(mx0, fmaxf(sc[nt][0], sc[nt][1]));
            mx1 = fmaxf(mx1, fmaxf(sc[nt][2], sc[nt][3]));
        }
#pragma unroll
        for (int off = 1; off <= 2; off <<= 1) {
            mx0 = fmaxf(mx0, __shfl_xor_sync(0xffffffffu, mx0, off));
            mx1 = fmaxf(mx1, __shfl_xor_sync(0xffffffffu, mx1, off));
        }
        float m0n = fmaxf(mi0, mx0), m1n = fmaxf(mi1, mx1);
        float a0 = __expf(mi0 - m0n), a1 = __expf(mi1 - m1n);
        mi0 = m0n; mi1 = m1n;
        float rs0 = 0.f, rs1 = 0.f;
#pragma unroll
        for (int nt = 0; nt < 16; nt++) {
            sc[nt][0] = __expf(sc[nt][0] - m0n);
            sc[nt][1] = __expf(sc[nt][1] - m0n);
            sc[nt][2] = __expf(sc[nt][2] - m1n);
            sc[nt][3] = __expf(sc[nt][3] - m1n);
            rs0 += sc[nt][0] + sc[nt][1];
            rs1 += sc[nt][2] + sc[nt][3];
        }
#pragma unroll
        for (int off = 1; off <= 2; off <<= 1) {
            rs0 += __shfl_xor_sync(0xffffffffu, rs0, off);
            rs1 += __shfl_xor_sync(0xffffffffu, rs1, off);
        }
        li0 = li0 * a0 + rs0;
        li1 = li1 * a1 + rs1;
#pragma unroll
        for (int nt = 0; nt < 8; nt++) {
            accO[nt][0] *= a0; accO[nt][1] *= a0;
            accO[nt][2] *= a1; accO[nt][3] *= a1;
        }

        // O += P.V : P from registers (C-frag == A-frag), B = Vt
#pragma unroll
        for (int g = 0; g < 8; g++) {
            uint32_t Ph[4], Pl[4];
#pragma unroll
            for (int t = 0; t < 2; t++)
#pragma unroll
                for (int r = 0; r < 2; r++) {
                    float x = sc[2 * g + t][2 * r], y = sc[2 * g + t][2 * r + 1];
                    __nv_bfloat162 hp = __floats2bfloat162_rn(x, y);
                    float2 hf = __bfloat1622float2(hp);
                    __nv_bfloat162 lp = __floats2bfloat162_rn(x - hf.x, y - hf.y);
                    Ph[t * 2 + r] = b2u(hp);
                    Pl[t * 2 + r] = b2u(lp);
                }
            const uint32_t kb = g * 32;
#pragma unroll
            for (int nt = 0; nt < 8; nt++) {
                uint32_t boff = (nt * 8 + lr) * VT_STR + kb + lc * 4;
                uint32_t Bh[2], Bl[2];
                Bh[0] = *(const uint32_t*)(sm + SM_VH + boff);
                Bh[1] = *(const uint32_t*)(sm + SM_VH + boff + 16);
                Bl[0] = *(const uint32_t*)(sm + SM_VL + boff);
                Bl[1] = *(const uint32_t*)(sm + SM_VL + boff + 16);
                mma16816(accO[nt], Ph, Bh);
                mma16816(accO[nt], Ph, Bl);
                mma16816(accO[nt], Pl, Bh);
            }
        }
    }

    // epilogue: normalize, write Ctx[b][row][h*64+d]
    float inv0 = 1.f / li0, inv1 = 1.f / li1;
    int row0 = qr0 + wq + lr;
#pragma unroll
    for (int nt = 0; nt < 8; nt++) {
        int col = h * HD + nt * 8 + lc * 2;
        *(float2*)(Ctx + ((size_t)(b * SS + row0)) * HIDDEN + col) =
            make_float2(accO[nt][0] * inv0, accO[nt][1] * inv0);
        *(float2*)(Ctx + ((size_t)(b * SS + row0 + 8)) * HIDDEN + col) =
            make_float2(accO[nt][2] * inv1, accO[nt][3] * inv1);
    }
}

extern "C" void kernel_launch(void* const* d_in, const int* in_sizes, int n_in,
                              void* d_out, int out_size)
{
    const float* q    = (const float*)d_in[0];
    const float* k    = (const float*)d_in[1];
    const float* v    = (const float*)d_in[2];
    const float* ab   = (const float*)d_in[3];
    const float* Wq   = (const float*)d_in[4];
    const float* bq   = (const float*)d_in[5];
    const float* Wk   = (const float*)d_in[6];
    const float* bk   = (const float*)d_in[7];
    const float* Wv   = (const float*)d_in[8];
    const float* bv   = (const float*)d_in[9];
    const float* Wo   = (const float*)d_in[10];
    const float* bo   = (const float*)d_in[11];
    const float* zoom = (const float*)d_in[12];

    float *Qh, *Kh, *Vt, *Ctx;
    cudaGetSymbolAddress((void**)&Qh,  g_Qh);
    cudaGetSymbolAddress((void**)&Kh,  g_Kh);
    cudaGetSymbolAddress((void**)&Vt,  g_Vt);
    cudaGetSymbolAddress((void**)&Ctx, g_Ctx);

    cudaFuncSetAttribute(gemm_tc_kernel,
                         cudaFuncAttributeMaxDynamicSharedMemorySize, GEMM_SMEM);
    cudaFuncSetAttribute(flash_tc_kernel,
                         cudaFuncAttributeMaxDynamicSharedMemorySize, FLASH_SMEM);

    dim3 gg(HIDDEN / 128, (BB * SS) / 128);
    gemm_tc_kernel<<<gg, 256, GEMM_SMEM>>>(q, Wq, bq, Qh, 0);
    gemm_tc_kernel<<<gg, 256, GEMM_SMEM>>>(k, Wk, bk, Kh, 0);
    gemm_tc_kernel<<<gg, 256, GEMM_SMEM>>>(v, Wv, bv, Vt, 2);

    dim3 gf(SS / 128, NH, BB);
    flash_tc_kernel<<<gf, 256, FLASH_SMEM>>>(Qh, Kh, Vt, ab, zoom, Ctx);

    gemm_tc_kernel<<<gg, 256, GEMM_SMEM>>>(Ctx, Wo, bo, (float*)d_out, 1);
}

// round 6
// speedup vs baseline: 2.3695x; 1.2123x over previous
#include <cuda_runtime.h>
#include <cuda_bf16.h>
#include <cstdint>
#include <cstring>

#define HIDDEN 1024
#define BB 8
#define SS 1024
#define NH 16
#define HD 64
#define SCALE 0.125f

// ---------------------------------------------------------------------------
// Scratch (no cudaMalloc allowed). All bf16 split hi/lo pairs.
// ---------------------------------------------------------------------------
#define NELEM (BB * SS * HIDDEN)     // 8M
__device__ __nv_bfloat16 g_qh[NELEM], g_ql[NELEM];
__device__ __nv_bfloat16 g_kh[NELEM], g_kl[NELEM];
__device__ __nv_bfloat16 g_vh[NELEM], g_vl[NELEM];
__device__ __nv_bfloat16 g_Wqh[HIDDEN*HIDDEN], g_Wql[HIDDEN*HIDDEN];
__device__ __nv_bfloat16 g_Wkh[HIDDEN*HIDDEN], g_Wkl[HIDDEN*HIDDEN];
__device__ __nv_bfloat16 g_Wvh[HIDDEN*HIDDEN], g_Wvl[HIDDEN*HIDDEN];
__device__ __nv_bfloat16 g_Woh[HIDDEN*HIDDEN], g_Wol[HIDDEN*HIDDEN];
__device__ __nv_bfloat16 g_Qsh[NELEM], g_Qsl[NELEM];   // [b,h,s,d]
__device__ __nv_bfloat16 g_Ksh[NELEM], g_Ksl[NELEM];   // [b,h,s,d]
__device__ __nv_bfloat16 g_Vth[NELEM], g_Vtl[NELEM];   // [b,h,d,s]
__device__ __nv_bfloat16 g_Ch[NELEM],  g_Cl[NELEM];    // ctx [b,s,1024]

__device__ __forceinline__ uint32_t b2u(__nv_bfloat162 h) {
    uint32_t u; memcpy(&u, &h, 4); return u;
}

__device__ __forceinline__ void mma16816(float* c, const uint32_t* a, const uint32_t* b) {
    asm volatile(
        "mma.sync.aligned.m16n8k16.row.col.f32.bf16.bf16.f32 "
        "{%0,%1,%2,%3}, {%4,%5,%6,%7}, {%8,%9}, {%0,%1,%2,%3};"
        : "+f"(c[0]), "+f"(c[1]), "+f"(c[2]), "+f"(c[3])
        : "r"(a[0]), "r"(a[1]), "r"(a[2]), "r"(a[3]), "r"(b[0]), "r"(b[1]));
}

__device__ __forceinline__ uint32_t smem_u32(const void* p) {
    uint32_t a;
    asm("{ .reg .u64 t; cvta.to.shared.u64 t, %1; cvt.u32.u64 %0, t; }" : "=r"(a) : "l"(p));
    return a;
}

#define CP_ASYNC16(dst, src) \
    asm volatile("cp.async.cg.shared.global [%0], [%1], 16;" :: "r"(dst), "l"(src))
#define CP_COMMIT() asm volatile("cp.async.commit_group;" ::: "memory")
#define CP_WAIT(n)  asm volatile("cp.async.wait_group %0;" :: "n"(n) : "memory")

__device__ __forceinline__ void split_store2(float x, float y,
                                             __nv_bfloat16* H, __nv_bfloat16* L, size_t off) {
    __nv_bfloat162 hp = __floats2bfloat162_rn(x, y);
    float2 hf = __bfloat1622float2(hp);
    __nv_bfloat162 lp = __floats2bfloat162_rn(x - hf.x, y - hf.y);
    *(uint32_t*)(H + off) = b2u(hp);
    *(uint32_t*)(L + off) = b2u(lp);
}

__device__ __forceinline__ void split_store1(float x, __nv_bfloat16* H, __nv_bfloat16* L, size_t off) {
    __nv_bfloat16 h = __float2bfloat16(x);
    H[off] = h;
    L[off] = __float2bfloat16(x - __bfloat162float(h));
}

// ---------------------------------------------------------------------------
// One-time fp32 -> bf16 hi/lo split
// ---------------------------------------------------------------------------
__global__ __launch_bounds__(256)
void split_kernel(const float* __restrict__ X, __nv_bfloat16* __restrict__ Xh,
                  __nv_bfloat16* __restrict__ Xl, int n4)
{
    int i = blockIdx.x * blockDim.x + threadIdx.x;
    if (i >= n4) return;
    float4 v = ((const float4*)X)[i];
    __nv_bfloat162 h01 = __floats2bfloat162_rn(v.x, v.y);
    __nv_bfloat162 h23 = __floats2bfloat162_rn(v.z, v.w);
    float2 f01 = __bfloat1622float2(h01);
    float2 f23 = __bfloat1622float2(h23);
    __nv_bfloat162 l01 = __floats2bfloat162_rn(v.x - f01.x, v.y - f01.y);
    __nv_bfloat162 l23 = __floats2bfloat162_rn(v.z - f23.x, v.w - f23.y);
    ((uint2*)Xh)[i] = make_uint2(b2u(h01), b2u(h23));
    ((uint2*)Xl)[i] = make_uint2(b2u(l01), b2u(l23));
}

// ---------------------------------------------------------------------------
// bf16 split GEMM, cp.async double-buffered.
// C[m,n] = sum_k A[m,k]*W[n,k] + bias[n]  (3-pass hi/lo accumulation)
// mode 0: split-bf16 out [b,h,s,d]; mode 1: fp32 row-major; mode 2: split Vt [b,h,d,s]
// ---------------------------------------------------------------------------
#define G_STG 73728      // bytes per stage (4 buffers x 128 rows x 144B)
#define G_AL 18432
#define G_BH 36864
#define G_BL 55296
#define GEMM_SMEM (2 * G_STG)

__global__ __launch_bounds__(256)
void gemm_bf16_kernel(const __nv_bfloat16* __restrict__ Ah, const __nv_bfloat16* __restrict__ Al,
                      const __nv_bfloat16* __restrict__ Wh, const __nv_bfloat16* __restrict__ Wl,
                      const float* __restrict__ bias, float* __restrict__ outF,
                      __nv_bfloat16* __restrict__ Oh, __nv_bfloat16* __restrict__ Ol, int mode)
{
    extern __shared__ char dsm[];
    const uint32_t su = smem_u32(dsm);
    const int tid = threadIdx.x;
    const int wid = tid >> 5, lane = tid & 31;
    const int lr = lane >> 2, lc = lane & 3;
    const int n0 = blockIdx.x * 128, m0 = blockIdx.y * 128;
    const int wm = (wid >> 2) * 64;
    const int wn = (wid & 3) * 32;

    float acc[4][4][4];
#pragma unroll
    for (int i = 0; i < 4; i++)
#pragma unroll
        for (int j = 0; j < 4; j++)
#pragma unroll
            for (int r = 0; r < 4; r++) acc[i][j][r] = 0.f;

    // stage loader: 4 buffers x 16KB, each thread 16 x 16B cp.async
#define G_LOAD(s, kt) do { \
    uint32_t base = su + (s) * G_STG; \
    _Pragma("unroll") \
    for (int li = 0; li < 4; li++) { \
        int idx = tid + li * 256; \
        int row = idx >> 3, seg = idx & 7; \
        uint32_t d0 = base + row * 144 + seg * 16; \
        const __nv_bfloat16* as = Ah + (size_t)(m0 + row) * HIDDEN + (kt) * 64 + seg * 8; \
        const __nv_bfloat16* als = Al + (size_t)(m0 + row) * HIDDEN + (kt) * 64 + seg * 8; \
        const __nv_bfloat16* ws = Wh + (size_t)(n0 + row) * HIDDEN + (kt) * 64 + seg * 8; \
        const __nv_bfloat16* wls = Wl + (size_t)(n0 + row) * HIDDEN + (kt) * 64 + seg * 8; \
        CP_ASYNC16(d0, as); \
        CP_ASYNC16(d0 + G_AL, als); \
        CP_ASYNC16(d0 + G_BH, ws); \
        CP_ASYNC16(d0 + G_BL, wls); \
    } \
} while (0)

    G_LOAD(0, 0);
    CP_COMMIT();

    for (int kt = 0; kt < 16; kt++) {
        if (kt < 15) {
            G_LOAD((kt + 1) & 1, kt + 1);
            CP_COMMIT();
            CP_WAIT(1);
        } else {
            CP_WAIT(0);
        }
        __syncthreads();

        char* sAh = dsm + (kt & 1) * G_STG;
        char* sAl = sAh + G_AL;
        char* sBh = sAh + G_BH;
        char* sBl = sAh + G_BL;

#pragma unroll
        for (int j = 0; j < 4; j++) {
            const uint32_t kb = j * 32;
            uint32_t Bhf[4][2], Blf[4][2];
#pragma unroll
            for (int jn = 0; jn < 4; jn++) {
                uint32_t boff = (wn + jn * 8 + lr) * 144 + kb + lc * 4;
                Bhf[jn][0] = *(const uint32_t*)(sBh + boff);
                Bhf[jn][1] = *(const uint32_t*)(sBh + boff + 16);
                Blf[jn][0] = *(const uint32_t*)(sBl + boff);
                Blf[jn][1] = *(const uint32_t*)(sBl + boff + 16);
            }
#pragma unroll
            for (int i = 0; i < 4; i++) {
                uint32_t aoff = (wm + i * 16 + lr) * 144 + kb + lc * 4;
                uint32_t Ahf[4], Alf[4];
                Ahf[0] = *(const uint32_t*)(sAh + aoff);
                Ahf[1] = *(const uint32_t*)(sAh + aoff + 8 * 144);
                Ahf[2] = *(const uint32_t*)(sAh + aoff + 16);
                Ahf[3] = *(const uint32_t*)(sAh + aoff + 8 * 144 + 16);
                Alf[0] = *(const uint32_t*)(sAl + aoff);
                Alf[1] = *(const uint32_t*)(sAl + aoff + 8 * 144);
                Alf[2] = *(const uint32_t*)(sAl + aoff + 16);
                Alf[3] = *(const uint32_t*)(sAl + aoff + 8 * 144 + 16);
#pragma unroll
                for (int jn = 0; jn < 4; jn++) {
                    mma16816(acc[i][jn], Ahf, Bhf[jn]);
                    mma16816(acc[i][jn], Ahf, Blf[jn]);
                    mma16816(acc[i][jn], Alf, Bhf[jn]);
                }
            }
        }
        __syncthreads();
    }

#pragma unroll
    for (int i = 0; i < 4; i++) {
#pragma unroll
        for (int jn = 0; jn < 4; jn++) {
            int row = m0 + wm + i * 16 + lr;
            int row8 = row + 8;
            int col = n0 + wn + jn * 8 + lc * 2;
            float x0 = acc[i][jn][0] + bias[col], y0 = acc[i][jn][1] + bias[col + 1];
            float x1 = acc[i][jn][2] + bias[col], y1 = acc[i][jn][3] + bias[col + 1];
            if (mode == 0) {
                int b0_ = row >> 10, s0_ = row & 1023;
                int b1_ = row8 >> 10, s1_ = row8 & 1023;
                int h = col >> 6, d = col & 63;
                split_store2(x0, y0, Oh, Ol, (((size_t)(b0_ * NH + h)) * SS + s0_) * HD + d);
                split_store2(x1, y1, Oh, Ol, (((size_t)(b1_ * NH + h)) * SS + s1_) * HD + d);
            } else if (mode == 1) {
                *(float2*)(outF + (size_t)row * HIDDEN + col) = make_float2(x0, y0);
                *(float2*)(outF + (size_t)row8 * HIDDEN + col) = make_float2(x1, y1);
            } else {
                int b0_ = row >> 10, s0_ = row & 1023;
                int s1_ = row8 & 1023;
                int h = col >> 6, d = col & 63;
                size_t base = (size_t)(b0_ * NH + h) * HD;
                split_store1(x0, Oh, Ol, (base + d) * SS + s0_);
                split_store1(y0, Oh, Ol, (base + d + 1) * SS + s0_);
                split_store1(x1, Oh, Ol, (base + d) * SS + s1_);
                split_store1(y1, Oh, Ol, (base + d + 1) * SS + s1_);
            }
        }
    }
}

// ---------------------------------------------------------------------------
// Tensor-core flash attention, pre-split bf16 inputs, cp.async pipelined K/V.
// 1 CTA per (b, h, 128 q rows); 8 warps x 16 rows; key chunks of 128.
// ---------------------------------------------------------------------------
#define F_QH 0
#define F_QL 18432
#define F_K(s) (36864 + (s) * 36864)    // KL at +18432
#define F_V(s) (110592 + (s) * 34816)   // VL at +17408
#define F_ZS 180224
#define FLASH_SMEM (F_ZS + 1152 * 4)

__global__ __launch_bounds__(256)
void flash_tc_kernel(const __nv_bfloat16* __restrict__ Qhg, const __nv_bfloat16* __restrict__ Qlg,
                     const __nv_bfloat16* __restrict__ Khg, const __nv_bfloat16* __restrict__ Klg,
                     const __nv_bfloat16* __restrict__ Vthg, const __nv_bfloat16* __restrict__ Vtlg,
                     const float* __restrict__ attn_bias, const float* __restrict__ zoom,
                     __nv_bfloat16* __restrict__ Ch, __nv_bfloat16* __restrict__ Cl)
{
    extern __shared__ char sm[];
    const uint32_t su = smem_u32(sm);
    float* zs = (float*)(sm + F_ZS);

    const int tid = threadIdx.x;
    const int wid = tid >> 5, lane = tid & 31;
    const int lr = lane >> 2, lc = lane & 3;
    const int wq = wid * 16;
    const int qt = blockIdx.x, h = blockIdx.y, b = blockIdx.z;
    const int qr0 = qt * 128;

    const __nv_bfloat16* gQh  = Qhg + (((size_t)(b * NH + h)) * SS + qr0) * HD;
    const __nv_bfloat16* gQl  = Qlg + (((size_t)(b * NH + h)) * SS + qr0) * HD;
    const __nv_bfloat16* gKh  = Khg + ((size_t)(b * NH + h)) * SS * HD;
    const __nv_bfloat16* gKl  = Klg + ((size_t)(b * NH + h)) * SS * HD;
    const __nv_bfloat16* gVth = Vthg + ((size_t)(b * NH + h)) * HD * SS;
    const __nv_bfloat16* gVtl = Vtlg + ((size_t)(b * NH + h)) * HD * SS;
    const float* gB = attn_bias + (size_t)b * SS * SS;

#define F_LOAD(s, t0) do { \
    _Pragma("unroll") \
    for (int li = 0; li < 4; li++) { \
        int idx = tid + li * 256; \
        int row = idx >> 3, seg = idx & 7; \
        uint32_t dk = su + F_K(s) + row * 144 + seg * 16; \
        CP_ASYNC16(dk,          gKh + (size_t)((t0) + row) * HD + seg * 8); \
        CP_ASYNC16(dk + 18432,  gKl + (size_t)((t0) + row) * HD + seg * 8); \
    } \
    _Pragma("unroll") \
    for (int li = 0; li < 4; li++) { \
        int idx = tid + li * 256; \
        int d = idx >> 4, seg = idx & 15; \
        uint32_t dv = su + F_V(s) + d * 272 + seg * 16; \
        CP_ASYNC16(dv,          gVth + (size_t)d * SS + (t0) + seg * 8); \
        CP_ASYNC16(dv + 17408,  gVtl + (size_t)d * SS + (t0) + seg * 8); \
    } \
} while (0)

    F_LOAD(0, 0);
    CP_COMMIT();

    // zoom staging + Q load (plain LDG, pre-split)
    for (int u = tid; u < 1152; u += 256)
        zs[u] = (qr0 + u < 2047) ? zoom[qr0 + u] : 0.f;
#pragma unroll
    for (int li = 0; li < 4; li++) {
        int idx = tid + li * 256;
        int row = idx >> 3, seg = idx & 7;
        *(uint4*)(sm + F_QH + row * 144 + seg * 16) = *(const uint4*)(gQh + row * HD + seg * 8);
        *(uint4*)(sm + F_QL + row * 144 + seg * 16) = *(const uint4*)(gQl + row * HD + seg * 8);
    }

    float accO[8][4];
#pragma unroll
    for (int nt = 0; nt < 8; nt++)
#pragma unroll
        for (int r = 0; r < 4; r++) accO[nt][r] = 0.f;
    float mi0 = -3.0e38f, mi1 = -3.0e38f, li0 = 0.f, li1 = 0.f;

    for (int kt = 0; kt < 8; kt++) {
        const int t0 = kt * 128;
        if (kt < 7) {
            F_LOAD((kt + 1) & 1, t0 + 128);
            CP_COMMIT();
            CP_WAIT(1);
        } else {
            CP_WAIT(0);
        }
        __syncthreads();

        char* sKh = sm + F_K(kt & 1);
        char* sKl = sKh + 18432;
        char* sVh = sm + F_V(kt & 1);
        char* sVl = sVh + 17408;

        // S = Q.K^T : warp computes 16 x 128
        float sc[16][4];
#pragma unroll
        for (int nt = 0; nt < 16; nt++)
#pragma unroll
            for (int r = 0; r < 4; r++) sc[nt][r] = 0.f;

#pragma unroll
        for (int ks = 0; ks < 4; ks++) {
            const uint32_t kb = ks * 32;
            uint32_t aoff = (wq + lr) * 144 + kb + lc * 4;
            uint32_t Ahf[4], Alf[4];
            Ahf[0] = *(const uint32_t*)(sm + F_QH + aoff);
            Ahf[1] = *(const uint32_t*)(sm + F_QH + aoff + 8 * 144);
            Ahf[2] = *(const uint32_t*)(sm + F_QH + aoff + 16);
            Ahf[3] = *(const uint32_t*)(sm + F_QH + aoff + 8 * 144 + 16);
            Alf[0] = *(const uint32_t*)(sm + F_QL + aoff);
            Alf[1] = *(const uint32_t*)(sm + F_QL + aoff + 8 * 144);
            Alf[2] = *(const uint32_t*)(sm + F_QL + aoff + 16);
            Alf[3] = *(const uint32_t*)(sm + F_QL + aoff + 8 * 144 + 16);
#pragma unroll
            for (int nt = 0; nt < 16; nt++) {
                uint32_t boff = (nt * 8 + lr) * 144 + kb + lc * 4;
                uint32_t Bh[2], Bl[2];
                Bh[0] = *(const uint32_t*)(sKh + boff);
                Bh[1] = *(const uint32_t*)(sKh + boff + 16);
                Bl[0] = *(const uint32_t*)(sKl + boff);
                Bl[1] = *(const uint32_t*)(sKl + boff + 16);
                mma16816(sc[nt], Ahf, Bh);
                mma16816(sc[nt], Ahf, Bl);
                mma16816(sc[nt], Alf, Bh);
            }
        }

        // scale + biases, online softmax
        const int row_l0 = wq + lr;
        float mx0 = -3.0e38f, mx1 = -3.0e38f;
#pragma unroll
        for (int nt = 0; nt < 16; nt++) {
            int keyg = t0 + nt * 8 + lc * 2;
            const float* bp = gB + (size_t)(qr0 + row_l0) * SS + keyg;
            float2 bv0 = *(const float2*)bp;
            float2 bv1 = *(const float2*)(bp + 8 * SS);
            int u0 = row_l0 - keyg + 1023;
            sc[nt][0] = fmaf(sc[nt][0], SCALE, bv0.x + zs[u0]);
            sc[nt][1] = fmaf(sc[nt][1], SCALE, bv0.y + zs[u0 - 1]);
            sc[nt][2] = fmaf(sc[nt][2], SCALE, bv1.x + zs[u0 + 8]);
            sc[nt][3] = fmaf(sc[nt][3], SCALE, bv1.y + zs[u0 + 7]);
            mx0 = fmaxf(mx0, fmaxf(sc[nt][0], sc[nt][1]));
            mx1 = fmaxf(mx1, fmaxf(sc[nt][2], sc[nt][3]));
        }
#pragma unroll
        for (int off = 1; off <= 2; off <<= 1) {
            mx0 = fmaxf(mx0, __shfl_xor_sync(0xffffffffu, mx0, off));
            mx1 = fmaxf(mx1, __shfl_xor_sync(0xffffffffu, mx1, off));
        }
        float m0n = fmaxf(mi0, mx0), m1n = fmaxf(mi1, mx1);
        float a0 = __expf(mi0 - m0n), a1 = __expf(mi1 - m1n);
        mi0 = m0n; mi1 = m1n;
        float rs0 = 0.f, rs1 = 0.f;
#pragma unroll
        for (int nt = 0; nt < 16; nt++) {
            sc[nt][0] = __expf(sc[nt][0] - m0n);
            sc[nt][1] = __expf(sc[nt][1] - m0n);
            sc[nt][2] = __expf(sc[nt][2] - m1n);
            sc[nt][3] = __expf(sc[nt][3] - m1n);
            rs0 += sc[nt][0] + sc[nt][1];
            rs1 += sc[nt][2] + sc[nt][3];
        }
#pragma unroll
        for (int off = 1; off <= 2; off <<= 1) {
            rs0 += __shfl_xor_sync(0xffffffffu, rs0, off);
            rs1 += __shfl_xor_sync(0xffffffffu, rs1, off);
        }
        li0 = li0 * a0 + rs0;
        li1 = li1 * a1 + rs1;
#pragma unroll
        for (int nt = 0; nt < 8; nt++) {
            accO[nt][0] *= a0; accO[nt][1] *= a0;
            accO[nt][2] *= a1; accO[nt][3] *= a1;
        }

        // O += P.V  (P in registers: C-frag == A-frag; hi/lo split of P)
#pragma unroll
        for (int g = 0; g < 8; g++) {
            uint32_t Ph[4], Pl[4];
#pragma unroll
            for (int t = 0; t < 2; t++)
#pragma unroll
                for (int r = 0; r < 2; r++) {
                    float x = sc[2 * g + t][2 * r], y = sc[2 * g + t][2 * r + 1];
                    __nv_bfloat162 hp = __floats2bfloat162_rn(x, y);
                    float2 hf = __bfloat1622float2(hp);
                    __nv_bfloat162 lp = __floats2bfloat162_rn(x - hf.x, y - hf.y);
                    Ph[t * 2 + r] = b2u(hp);
                    Pl[t * 2 + r] = b2u(lp);
                }
            const uint32_t kb = g * 32;
#pragma unroll
            for (int nt = 0; nt < 8; nt++) {
                uint32_t boff = (nt * 8 + lr) * 272 + kb + lc * 4;
                uint32_t Bh[2], Bl[2];
                Bh[0] = *(const uint32_t*)(sVh + boff);
                Bh[1] = *(const uint32_t*)(sVh + boff + 16);
                Bl[0] = *(const uint32_t*)(sVl + boff);
                Bl[1] = *(const uint32_t*)(sVl + boff + 16);
                mma16816(accO[nt], Ph, Bh);
                mma16816(accO[nt], Ph, Bl);
                mma16816(accO[nt], Pl, Bh);
            }
        }
        __syncthreads();
    }

    // epilogue: normalize, write split-bf16 Ctx[b][row][h*64+d]
    float inv0 = 1.f / li0, inv1 = 1.f / li1;
    int row0 = qr0 + wq + lr;
#pragma unroll
    for (int nt = 0; nt < 8; nt++) {
        int col = h * HD + nt * 8 + lc * 2;
        split_store2(accO[nt][0] * inv0, accO[nt][1] * inv0, Ch, Cl,
                     ((size_t)(b * SS + row0)) * HIDDEN + col);
        split_store2(accO[nt][2] * inv1, accO[nt][3] * inv1, Ch, Cl,
                     ((size_t)(b * SS + row0 + 8)) * HIDDEN + col);
    }
}

extern "C" void kernel_launch(void* const* d_in, const int* in_sizes, int n_in,
                              void* d_out, int out_size)
{
    const float* q    = (const float*)d_in[0];
    const float* k    = (const float*)d_in[1];
    const float* v    = (const float*)d_in[2];
    const float* ab   = (const float*)d_in[3];
    const float* Wq   = (const float*)d_in[4];
    const float* bq   = (const float*)d_in[5];
    const float* Wk   = (const float*)d_in[6];
    const float* bk   = (const float*)d_in[7];
    const float* Wv   = (const float*)d_in[8];
    const float* bv   = (const float*)d_in[9];
    const float* Wo   = (const float*)d_in[10];
    const float* bo   = (const float*)d_in[11];
    const float* zoom = (const float*)d_in[12];

    __nv_bfloat16 *qh, *ql, *kh, *kl, *vh, *vl;
    __nv_bfloat16 *Wqh, *Wql, *Wkh, *Wkl, *Wvh, *Wvl, *Woh, *Wol;
    __nv_bfloat16 *Qsh, *Qsl, *Ksh, *Ksl, *Vth, *Vtl, *Ch, *Cl;
    cudaGetSymbolAddress((void**)&qh, g_qh);   cudaGetSymbolAddress((void**)&ql, g_ql);
    cudaGetSymbolAddress((void**)&kh, g_kh);   cudaGetSymbolAddress((void**)&kl, g_kl);
    cudaGetSymbolAddress((void**)&vh, g_vh);   cudaGetSymbolAddress((void**)&vl, g_vl);
    cudaGetSymbolAddress((void**)&Wqh, g_Wqh); cudaGetSymbolAddress((void**)&Wql, g_Wql);
    cudaGetSymbolAddress((void**)&Wkh, g_Wkh); cudaGetSymbolAddress((void**)&Wkl, g_Wkl);
    cudaGetSymbolAddress((void**)&Wvh, g_Wvh); cudaGetSymbolAddress((void**)&Wvl, g_Wvl);
    cudaGetSymbolAddress((void**)&Woh, g_Woh); cudaGetSymbolAddress((void**)&Wol, g_Wol);
    cudaGetSymbolAddress((void**)&Qsh, g_Qsh); cudaGetSymbolAddress((void**)&Qsl, g_Qsl);
    cudaGetSymbolAddress((void**)&Ksh, g_Ksh); cudaGetSymbolAddress((void**)&Ksl, g_Ksl);
    cudaGetSymbolAddress((void**)&Vth, g_Vth); cudaGetSymbolAddress((void**)&Vtl, g_Vtl);
    cudaGetSymbolAddress((void**)&Ch, g_Ch);   cudaGetSymbolAddress((void**)&Cl, g_Cl);

    cudaFuncSetAttribute(gemm_bf16_kernel,
                         cudaFuncAttributeMaxDynamicSharedMemorySize, GEMM_SMEM);
    cudaFuncSetAttribute(flash_tc_kernel,
                         cudaFuncAttributeMaxDynamicSharedMemorySize, FLASH_SMEM);

    // one-time splits
    split_kernel<<<NELEM / 1024, 256>>>(q, qh, ql, NELEM / 4);
    split_kernel<<<NELEM / 1024, 256>>>(k, kh, kl, NELEM / 4);
    split_kernel<<<NELEM / 1024, 256>>>(v, vh, vl, NELEM / 4);
    split_kernel<<<HIDDEN * HIDDEN / 1024, 256>>>(Wq, Wqh, Wql, HIDDEN * HIDDEN / 4);
    split_kernel<<<HIDDEN * HIDDEN / 1024, 256>>>(Wk, Wkh, Wkl, HIDDEN * HIDDEN / 4);
    split_kernel<<<HIDDEN * HIDDEN / 1024, 256>>>(Wv, Wvh, Wvl, HIDDEN * HIDDEN / 4);
    split_kernel<<<HIDDEN * HIDDEN / 1024, 256>>>(Wo, Woh, Wol, HIDDEN * HIDDEN / 4);

    dim3 gg(HIDDEN / 128, (BB * SS) / 128);
    gemm_bf16_kernel<<<gg, 256, GEMM_SMEM>>>(qh, ql, Wqh, Wql, bq, nullptr, Qsh, Qsl, 0);
    gemm_bf16_kernel<<<gg, 256, GEMM_SMEM>>>(kh, kl, Wkh, Wkl, bk, nullptr, Ksh, Ksl, 0);
    gemm_bf16_kernel<<<gg, 256, GEMM_SMEM>>>(vh, vl, Wvh, Wvl, bv, nullptr, Vth, Vtl, 2);

    dim3 gf(SS / 128, NH, BB);
    flash_tc_kernel<<<gf, 256, FLASH_SMEM>>>(Qsh, Qsl, Ksh, Ksl, Vth, Vtl, ab, zoom, Ch, Cl);

    gemm_bf16_kernel<<<gg, 256, GEMM_SMEM>>>(Ch, Cl, Woh, Wol, bo, (float*)d_out,
                                             nullptr, nullptr, 1);
}